// round 15
// baseline (speedup 1.0000x reference)
#include <cuda_runtime.h>
#include <cuda_fp16.h>
#include <math.h>

#define IN_DIM 128
#define HID    64
#define MAXN   100000
#define MAXE   1600000

// ---------------- scratch (static device globals; no allocation) ----------------
__device__ __align__(16) float  g_h  [(size_t)MAXN * HID];   // pre-layer input (fp32)
__device__ __align__(16) __half g_hwA[(size_t)MAXN * HID];   // h @ W ping (fp16)
__device__ __align__(16) __half g_hwB[(size_t)MAXN * HID];   // h @ W pong (fp16)
__device__ float g_dinv[MAXN];
__device__ int   g_cnt[MAXN];        // in-degree (without self loop)
__device__ int   g_base[MAXN];       // CSR row start
__device__ int   g_cursor[MAXN];     // fill cursor
__device__ int   g_total;            // atomic allocation counter
__device__ __align__(16) int2 g_csr[MAXE];  // (src, nrm bits) per CSR slot

// ================= CSR build (scan-free: atomic row allocation) =================
__global__ void zero_cnt_kernel(int n) {
    int i = blockIdx.x * blockDim.x + threadIdx.x;
    if (i < n) g_cnt[i] = 0;
    if (i == 0) g_total = 0;
}

__global__ void hist_kernel(const int* __restrict__ dst, int E) {
    int e = blockIdx.x * blockDim.x + threadIdx.x;
    if (e < E) atomicAdd(&g_cnt[dst[e]], 1);
}

__global__ void alloc_base_kernel(int n) {
    int i = blockIdx.x * blockDim.x + threadIdx.x;
    if (i >= n) return;
    int c = g_cnt[i];
    int base = atomicAdd(&g_total, c);   // contiguous row, arbitrary placement
    g_base[i]   = base;
    g_cursor[i] = base;
    g_dinv[i]   = rsqrtf((float)c + 1.0f);   // deg of A+I
}

// premultiplied edge norm: nrm = dinv[src]*dinv[dst]
__global__ void fill_kernel(const int* __restrict__ src,
                            const int* __restrict__ dst, int E) {
    int e = blockIdx.x * blockDim.x + threadIdx.x;
    if (e >= E) return;
    int d = dst[e];
    int s = src[e];
    int pos = atomicAdd(&g_cursor[d], 1);
    float nrm = g_dinv[s] * g_dinv[d];
    g_csr[pos] = make_int2(s, __float_as_int(nrm));   // one 8B store
}

// ================= register-blocked GEMM (R8/R11-proven: 4x4, 256 thr) ==========
template<int K>
__device__ __forceinline__ void gemm_rb_compute(const float* __restrict__ A,
                                                const float* __restrict__ W,
                                                int n, int row0,
                                                float4& a0, float4& a1,
                                                float4& a2, float4& a3) {
    __shared__ float  As[64][68];
    __shared__ float4 Ws[64][16];

    const int t  = threadIdx.x;
    const int tr = (t >> 4) << 2;
    const int tc = t & 15;

    for (int kh = 0; kh < K; kh += 64) {
        #pragma unroll
        for (int i = t; i < 1024; i += 256) {
            int k = i >> 4, c = i & 15;
            Ws[k][c] = ((const float4*)(W + (size_t)(kh + k) * HID))[c];
        }
        #pragma unroll
        for (int i = t; i < 1024; i += 256) {
            int r = i >> 4, c = i & 15;
            float4 v = make_float4(0.f,0.f,0.f,0.f);
            int row = row0 + r;
            if (row < n) v = *(const float4*)(A + (size_t)row * K + kh + c * 4);
            As[r][c*4+0] = v.x; As[r][c*4+1] = v.y;
            As[r][c*4+2] = v.z; As[r][c*4+3] = v.w;
        }
        __syncthreads();

        #pragma unroll 16
        for (int k = 0; k < 64; k++) {
            float4 w = Ws[k][tc];
            float x0 = As[tr+0][k];
            float x1 = As[tr+1][k];
            float x2 = As[tr+2][k];
            float x3 = As[tr+3][k];
            a0.x += x0*w.x; a0.y += x0*w.y; a0.z += x0*w.z; a0.w += x0*w.w;
            a1.x += x1*w.x; a1.y += x1*w.y; a1.z += x1*w.z; a1.w += x1*w.w;
            a2.x += x2*w.x; a2.y += x2*w.y; a2.z += x2*w.z; a2.w += x2*w.w;
            a3.x += x3*w.x; a3.y += x3*w.y; a3.z += x3*w.z; a3.w += x3*w.w;
        }
        __syncthreads();
    }
}

// feature_pre: x[n,128] @ W_pre + b -> g_h (fp32). Globals referenced in device
// code only (GB300 ATS silently dereferences host-side shadow symbols).
__global__ void gemm_pre_rb_kernel(const float* __restrict__ x,
                                   const float* __restrict__ W,
                                   const float* __restrict__ bias, int n) {
    float4 a0 = make_float4(0.f,0.f,0.f,0.f), a1 = a0, a2 = a0, a3 = a0;
    int row0 = blockIdx.x * 64;
    gemm_rb_compute<IN_DIM>(x, W, n, row0, a0, a1, a2, a3);

    const int tr = (threadIdx.x >> 4) << 2, tc = threadIdx.x & 15;
    float4 b = ((const float4*)bias)[tc];
    a0.x += b.x; a0.y += b.y; a0.z += b.z; a0.w += b.w;
    a1.x += b.x; a1.y += b.y; a1.z += b.z; a1.w += b.w;
    a2.x += b.x; a2.y += b.y; a2.z += b.z; a2.w += b.w;
    a3.x += b.x; a3.y += b.y; a3.z += b.z; a3.w += b.w;

    if (row0 + tr + 0 < n) ((float4*)(g_h + (size_t)(row0+tr+0) * HID))[tc] = a0;
    if (row0 + tr + 1 < n) ((float4*)(g_h + (size_t)(row0+tr+1) * HID))[tc] = a1;
    if (row0 + tr + 2 < n) ((float4*)(g_h + (size_t)(row0+tr+2) * HID))[tc] = a2;
    if (row0 + tr + 3 < n) ((float4*)(g_h + (size_t)(row0+tr+3) * HID))[tc] = a3;
}

// layer-1 GEMM: g_h[n,64] @ W1 -> g_hwA (fp16)
__global__ void gemm_layer1_kernel(const float* __restrict__ W, int n) {
    float4 a0 = make_float4(0.f,0.f,0.f,0.f), a1 = a0, a2 = a0, a3 = a0;
    int row0 = blockIdx.x * 64;
    gemm_rb_compute<HID>(g_h, W, n, row0, a0, a1, a2, a3);

    const int tr = (threadIdx.x >> 4) << 2, tc = threadIdx.x & 15;
    float4 accs[4] = {a0, a1, a2, a3};
    #pragma unroll
    for (int j = 0; j < 4; j++) {
        int row = row0 + tr + j;
        if (row < n) {
            __half2 h0 = __floats2half2_rn(accs[j].x, accs[j].y);
            __half2 h1 = __floats2half2_rn(accs[j].z, accs[j].w);
            uint2 pack = make_uint2(*reinterpret_cast<const unsigned*>(&h0),
                                    *reinterpret_cast<const unsigned*>(&h1));
            ((uint2*)(g_hwA + (size_t)row * HID))[tc] = pack;
        }
    }
}

// ============ fused gather + next-layer GEMM (8 nodes/block, 8 warps) ===========
// Per warp (R11-proven body): acc = hw_in[node]*dinv^2 + b + sum_e hw_in[src]*nrm.
// Non-FINAL: relu -> smem Hs[8][64] -> in-block 8x64 @ 64x64 GEMM (issue work
// poured into the gather's idle latency slots) -> hw_out fp16.
// FINAL: L2-normalize -> out. Ping-pong buffers picked IN DEVICE CODE via sel.
template<bool FINAL>
__global__ void gather_gemm_kernel(const float* __restrict__ bias,
                                   const float* __restrict__ Wn,
                                   float* __restrict__ out,
                                   int sel, int n) {
    __shared__ float  Hs[8][64];
    __shared__ float2 Ws2[64][32];   // W_next as col pairs, 16 KB

    const __half2* hw2    = (const __half2*)(sel ? g_hwB : g_hwA);
    __half*        hw_out = sel ? g_hwA : g_hwB;

    int tid  = threadIdx.x;
    int wid  = tid >> 5;
    int lane = tid & 31;
    int w    = blockIdx.x * 8 + wid;

    if (!FINAL) {   // stage W_next while gather loads are in flight
        #pragma unroll
        for (int i = tid; i < 64 * 32; i += 256) {
            int k = i >> 5, c = i & 31;
            Ws2[k][c] = ((const float2*)(Wn + k * HID))[c];
        }
    }

    float2 acc = make_float2(0.f, 0.f);
    if (w < n) {
        float dd = g_dinv[w];
        float2 self = __half22float2(hw2[(size_t)w * 32 + lane]);
        float2 b    = ((const float2*)bias)[lane];
        acc.x = self.x * dd * dd + b.x;
        acc.y = self.y * dd * dd + b.y;

        int jbeg = g_base[w];
        int jend = jbeg + g_cnt[w];
        for (int j0 = jbeg; j0 < jend; j0 += 32) {
            int j = j0 + lane;
            int   s  = 0;
            float nm = 0.f;
            if (j < jend) {
                int2 rec = g_csr[j];
                s  = rec.x;
                nm = __int_as_float(rec.y);
            }
            int m = min(32, jend - j0);
            for (int i = 0; i < m; i++) {
                int   si = __shfl_sync(0xffffffffu, s,  i);
                float ni = __shfl_sync(0xffffffffu, nm, i);
                float2 v = __half22float2(hw2[(size_t)si * 32 + lane]);
                acc.x += v.x * ni;
                acc.y += v.y * ni;
            }
        }
    }

    if (FINAL) {
        if (w < n) {
            float ss = acc.x * acc.x + acc.y * acc.y;
            #pragma unroll
            for (int o = 16; o; o >>= 1) ss += __shfl_xor_sync(0xffffffffu, ss, o);
            float sc = 1.0f / fmaxf(sqrtf(ss), 1e-12f);
            float2 r; r.x = acc.x * sc; r.y = acc.y * sc;
            ((float2*)out)[(size_t)w * 32 + lane] = r;
        }
        return;
    }

    // relu -> stage activations
    Hs[wid][lane*2+0] = (w < n) ? fmaxf(acc.x, 0.f) : 0.f;
    Hs[wid][lane*2+1] = (w < n) ? fmaxf(acc.y, 0.f) : 0.f;
    __syncthreads();

    // in-block mini-GEMM: thread = row (tid>>5) x col pair (tid&31)
    int r  = tid >> 5;
    int c2 = tid & 31;
    float o0 = 0.f, o1 = 0.f;
    #pragma unroll 16
    for (int k = 0; k < HID; k++) {
        float h  = Hs[r][k];        // warp-broadcast
        float2 wv = Ws2[k][c2];     // coalesced
        o0 += h * wv.x;
        o1 += h * wv.y;
    }
    int row = blockIdx.x * 8 + r;
    if (row < n) {
        __half2 hp = __floats2half2_rn(o0, o1);
        ((__half2*)(hw_out + (size_t)row * HID))[c2] = hp;
    }
}

// ================= host launcher (forked graph: CSR || GEMM chain) ==============
extern "C" void kernel_launch(void* const* d_in, const int* in_sizes, int n_in,
                              void* d_out, int out_size) {
    const float* x     = (const float*)d_in[0];
    const int*   ei    = (const int*)d_in[1];   // int32 (JAX x64 disabled)
    const float* W_pre = (const float*)d_in[2];
    const float* b_pre = (const float*)d_in[3];
    const float* Wl[3] = {(const float*)d_in[4], (const float*)d_in[6], (const float*)d_in[8]};
    const float* Bl[3] = {(const float*)d_in[5], (const float*)d_in[7], (const float*)d_in[9]};
    float* out = (float*)d_out;

    int n = in_sizes[0] / IN_DIM;    // 100000
    int E = in_sizes[1] / 2;         // 1600000
    const int* src_idx = ei;
    const int* dst_idx = ei + E;

    // lazily-created side stream + fork/join events (first call = correctness run)
    static cudaStream_t s_side = nullptr;
    static cudaEvent_t  s_fork = nullptr, s_join = nullptr;
    if (!s_side) {
        cudaStreamCreateWithFlags(&s_side, cudaStreamNonBlocking);
        cudaEventCreateWithFlags(&s_fork, cudaEventDisableTiming);
        cudaEventCreateWithFlags(&s_join, cudaEventDisableTiming);
    }

    int gemm_blocks   = (n + 63) / 64;
    int fused_blocks  = (n + 7) / 8;

    // ---- fork: CSR build on side stream ----
    cudaEventRecord(s_fork, 0);
    cudaStreamWaitEvent(s_side, s_fork, 0);
    zero_cnt_kernel<<<(n + 255) / 256, 256, 0, s_side>>>(n);
    hist_kernel<<<(E + 255) / 256, 256, 0, s_side>>>(dst_idx, E);
    alloc_base_kernel<<<(n + 255) / 256, 256, 0, s_side>>>(n);
    fill_kernel<<<(E + 255) / 256, 256, 0, s_side>>>(src_idx, dst_idx, E);
    cudaEventRecord(s_join, s_side);

    // ---- main stream: GEMM chain (independent of CSR) ----
    gemm_pre_rb_kernel<<<gemm_blocks, 256>>>(x, W_pre, b_pre, n);
    gemm_layer1_kernel<<<gemm_blocks, 256>>>(Wl[0], n);   // -> g_hwA

    // ---- join: gathers need both chains ----
    cudaStreamWaitEvent(0, s_join, 0);

    // layer 1 gather + layer-2 GEMM fused: hwA -> hwB
    gather_gemm_kernel<false><<<fused_blocks, 256>>>(Bl[0], Wl[1], nullptr, 0, n);
    // layer 2 gather + layer-3 GEMM fused: hwB -> hwA
    gather_gemm_kernel<false><<<fused_blocks, 256>>>(Bl[1], Wl[2], nullptr, 1, n);
    // layer 3 gather + L2 normalize: hwA -> out
    gather_gemm_kernel<true><<<fused_blocks, 256>>>(Bl[2], nullptr, out, 0, n);
}

// round 16
// speedup vs baseline: 1.2257x; 1.2257x over previous
#include <cuda_runtime.h>
#include <cuda_fp16.h>
#include <math.h>

#define IN_DIM 128
#define HID    64
#define MAXN   100000
#define MAXE   1600000

// ---------------- scratch (static device globals; no allocation) ----------------
__device__ __align__(16) float  g_h   [(size_t)MAXN * HID];  // layer input (fp32)
__device__ __align__(16) __half g_hw_h[(size_t)MAXN * HID];  // h @ W (fp16 storage)
__device__ float g_dinv[MAXN];
__device__ int   g_cnt[MAXN];        // in-degree (without self loop)
__device__ int   g_base[MAXN];       // CSR row start
__device__ int   g_cursor[MAXN];     // fill cursor
__device__ int   g_total;            // atomic allocation counter
__device__ __align__(16) int2 g_csr[MAXE];  // (src, nrm bits) per CSR slot

// ================= CSR build (scan-free: atomic row allocation) =================
__global__ void zero_cnt_kernel(int n) {
    int i = blockIdx.x * blockDim.x + threadIdx.x;
    if (i < n) g_cnt[i] = 0;
    if (i == 0) g_total = 0;
}

__global__ void hist_kernel(const int* __restrict__ dst, int E) {
    int e = blockIdx.x * blockDim.x + threadIdx.x;
    if (e < E) atomicAdd(&g_cnt[dst[e]], 1);
}

__global__ void alloc_base_kernel(int n) {
    int i = blockIdx.x * blockDim.x + threadIdx.x;
    if (i >= n) return;
    int c = g_cnt[i];
    int base = atomicAdd(&g_total, c);   // contiguous row, arbitrary placement
    g_base[i]   = base;
    g_cursor[i] = base;
    g_dinv[i]   = rsqrtf((float)c + 1.0f);   // deg of A+I
}

// premultiplied edge norm: nrm = dinv[src]*dinv[dst]
__global__ void fill_kernel(const int* __restrict__ src,
                            const int* __restrict__ dst, int E) {
    int e = blockIdx.x * blockDim.x + threadIdx.x;
    if (e >= E) return;
    int d = dst[e];
    int s = src[e];
    int pos = atomicAdd(&g_cursor[d], 1);
    float nrm = g_dinv[s] * g_dinv[d];
    g_csr[pos] = make_int2(s, __float_as_int(nrm));   // one 8B store
}

// ========== gemm_pre: 128-row tile, 8 rows x 4 cols/thread, 256 threads =========
// Targeted at gemm_pre's measured issue=54.6% (stall-exposed, NOT at FFMA
// ceiling): 32 FMA per 9 LDS. k staged 32-wide; As stride 33 (8-row broadcast
// groups 8 banks apart). Layer GEMMs keep the 4x4 tile (at issue ceiling).
__global__ void gemm_pre_rb_kernel(const float* __restrict__ x,
                                   const float* __restrict__ W,
                                   const float* __restrict__ bias, int n) {
    __shared__ float  As[128][33];
    __shared__ float4 Ws[32][16];

    const int t  = threadIdx.x;
    const int tr = (t >> 4) << 3;    // 0,8,...,120
    const int tc = t & 15;
    const int row0 = blockIdx.x * 128;

    float4 acc[8];
    #pragma unroll
    for (int j = 0; j < 8; j++) acc[j] = make_float4(0.f,0.f,0.f,0.f);

    for (int kh = 0; kh < IN_DIM; kh += 32) {
        #pragma unroll
        for (int i = t; i < 512; i += 256) {
            int k = i >> 4, c = i & 15;
            Ws[k][c] = ((const float4*)(W + (size_t)(kh + k) * HID))[c];
        }
        #pragma unroll
        for (int i = t; i < 1024; i += 256) {
            int r = i >> 3, c = i & 7;      // 128 rows x 8 float4 (32 k-values)
            float4 v = make_float4(0.f,0.f,0.f,0.f);
            int row = row0 + r;
            if (row < n) v = *(const float4*)(x + (size_t)row * IN_DIM + kh + c * 4);
            As[r][c*4+0] = v.x; As[r][c*4+1] = v.y;
            As[r][c*4+2] = v.z; As[r][c*4+3] = v.w;
        }
        __syncthreads();

        #pragma unroll 8
        for (int k = 0; k < 32; k++) {
            float4 w = Ws[k][tc];
            #pragma unroll
            for (int j = 0; j < 8; j++) {
                float xx = As[tr + j][k];
                acc[j].x += xx * w.x; acc[j].y += xx * w.y;
                acc[j].z += xx * w.z; acc[j].w += xx * w.w;
            }
        }
        __syncthreads();
    }

    float4 b = ((const float4*)bias)[tc];
    #pragma unroll
    for (int j = 0; j < 8; j++) {
        int row = row0 + tr + j;
        if (row < n) {
            float4 r;
            r.x = acc[j].x + b.x; r.y = acc[j].y + b.y;
            r.z = acc[j].z + b.z; r.w = acc[j].w + b.w;
            ((float4*)(g_h + (size_t)row * HID))[tc] = r;
        }
    }
}

// ===== layer GEMM (R11-proven 4x4 tile, at FFMA issue ceiling — unchanged) ======
// g_h[n,64] @ W -> g_hw_h (fp16 storage). Globals referenced in device code only
// (GB300 ATS silently dereferences host-side shadow symbols).
__global__ void gemm_layer_rb_kernel(const float* __restrict__ W, int n) {
    __shared__ float  As[64][68];
    __shared__ float4 Ws[64][16];

    const int t  = threadIdx.x;
    const int tr = (t >> 4) << 2;
    const int tc = t & 15;
    const int row0 = blockIdx.x * 64;

    float4 a0 = make_float4(0.f,0.f,0.f,0.f), a1 = a0, a2 = a0, a3 = a0;

    #pragma unroll
    for (int i = t; i < 1024; i += 256) {
        int k = i >> 4, c = i & 15;
        Ws[k][c] = ((const float4*)(W + (size_t)k * HID))[c];
    }
    #pragma unroll
    for (int i = t; i < 1024; i += 256) {
        int r = i >> 4, c = i & 15;
        float4 v = make_float4(0.f,0.f,0.f,0.f);
        int row = row0 + r;
        if (row < n) v = *(const float4*)(g_h + (size_t)row * HID + c * 4);
        As[r][c*4+0] = v.x; As[r][c*4+1] = v.y;
        As[r][c*4+2] = v.z; As[r][c*4+3] = v.w;
    }
    __syncthreads();

    #pragma unroll 16
    for (int k = 0; k < 64; k++) {
        float4 w = Ws[k][tc];
        float x0 = As[tr+0][k];
        float x1 = As[tr+1][k];
        float x2 = As[tr+2][k];
        float x3 = As[tr+3][k];
        a0.x += x0*w.x; a0.y += x0*w.y; a0.z += x0*w.z; a0.w += x0*w.w;
        a1.x += x1*w.x; a1.y += x1*w.y; a1.z += x1*w.z; a1.w += x1*w.w;
        a2.x += x2*w.x; a2.y += x2*w.y; a2.z += x2*w.z; a2.w += x2*w.w;
        a3.x += x3*w.x; a3.y += x3*w.y; a3.z += x3*w.z; a3.w += x3*w.w;
    }

    float4 accs[4] = {a0, a1, a2, a3};
    #pragma unroll
    for (int j = 0; j < 4; j++) {
        int row = row0 + tr + j;
        if (row < n) {
            __half2 h0 = __floats2half2_rn(accs[j].x, accs[j].y);
            __half2 h1 = __floats2half2_rn(accs[j].z, accs[j].w);
            uint2 pack = make_uint2(*reinterpret_cast<const unsigned*>(&h0),
                                    *reinterpret_cast<const unsigned*>(&h1));
            ((uint2*)(g_hw_h + (size_t)row * HID))[tc] = pack;
        }
    }
}

// ================= fused gather (warp per node) — R11-proven ====================
// acc = hw[node]*dinv^2 + b  +  sum_{e: dst=node} hw[src_e] * nrm_e
template<bool FINAL>
__global__ void gather_kernel(const float* __restrict__ bias,
                              float* __restrict__ out, int n) {
    int w    = (blockIdx.x * blockDim.x + threadIdx.x) >> 5;
    int lane = threadIdx.x & 31;
    if (w >= n) return;

    const __half2* hw2 = (const __half2*)g_hw_h;   // row = 32 half2
    float dd = g_dinv[w];
    float2 self = __half22float2(hw2[(size_t)w * 32 + lane]);
    float2 b    = ((const float2*)bias)[lane];
    float2 acc;
    acc.x = self.x * dd * dd + b.x;
    acc.y = self.y * dd * dd + b.y;

    int jbeg = g_base[w];
    int jend = jbeg + g_cnt[w];
    for (int j0 = jbeg; j0 < jend; j0 += 32) {
        int j = j0 + lane;
        int   s  = 0;
        float nm = 0.f;
        if (j < jend) {
            int2 rec = g_csr[j];
            s  = rec.x;
            nm = __int_as_float(rec.y);
        }
        int m = min(32, jend - j0);
        for (int i = 0; i < m; i++) {
            int   si = __shfl_sync(0xffffffffu, s,  i);
            float ni = __shfl_sync(0xffffffffu, nm, i);
            float2 v = __half22float2(hw2[(size_t)si * 32 + lane]);
            acc.x += v.x * ni;
            acc.y += v.y * ni;
        }
    }

    if (!FINAL) {
        float2 r;
        r.x = fmaxf(acc.x, 0.f);
        r.y = fmaxf(acc.y, 0.f);
        ((float2*)g_h)[(size_t)w * 32 + lane] = r;
    } else {
        float ss = acc.x * acc.x + acc.y * acc.y;
        #pragma unroll
        for (int o = 16; o; o >>= 1) ss += __shfl_xor_sync(0xffffffffu, ss, o);
        float sc = 1.0f / fmaxf(sqrtf(ss), 1e-12f);
        float2 r; r.x = acc.x * sc; r.y = acc.y * sc;
        ((float2*)out)[(size_t)w * 32 + lane] = r;
    }
}

// ================= host launcher (forked graph: CSR || GEMM chain) ==============
extern "C" void kernel_launch(void* const* d_in, const int* in_sizes, int n_in,
                              void* d_out, int out_size) {
    const float* x     = (const float*)d_in[0];
    const int*   ei    = (const int*)d_in[1];   // int32 (JAX x64 disabled)
    const float* W_pre = (const float*)d_in[2];
    const float* b_pre = (const float*)d_in[3];
    const float* Wl[3] = {(const float*)d_in[4], (const float*)d_in[6], (const float*)d_in[8]};
    const float* Bl[3] = {(const float*)d_in[5], (const float*)d_in[7], (const float*)d_in[9]};
    float* out = (float*)d_out;

    int n = in_sizes[0] / IN_DIM;    // 100000
    int E = in_sizes[1] / 2;         // 1600000
    const int* src_idx = ei;
    const int* dst_idx = ei + E;

    // lazily-created side stream + fork/join events (first call = correctness run)
    static cudaStream_t s_side = nullptr;
    static cudaEvent_t  s_fork = nullptr, s_join = nullptr;
    if (!s_side) {
        cudaStreamCreateWithFlags(&s_side, cudaStreamNonBlocking);
        cudaEventCreateWithFlags(&s_fork, cudaEventDisableTiming);
        cudaEventCreateWithFlags(&s_join, cudaEventDisableTiming);
    }

    int pre_blocks    = (n + 127) / 128;
    int layer_blocks  = (n + 63) / 64;
    int gather_blocks = (n * 32 + 255) / 256;

    // ---- fork: CSR build on side stream ----
    cudaEventRecord(s_fork, 0);
    cudaStreamWaitEvent(s_side, s_fork, 0);
    zero_cnt_kernel<<<(n + 255) / 256, 256, 0, s_side>>>(n);
    hist_kernel<<<(E + 255) / 256, 256, 0, s_side>>>(dst_idx, E);
    alloc_base_kernel<<<(n + 255) / 256, 256, 0, s_side>>>(n);
    fill_kernel<<<(E + 255) / 256, 256, 0, s_side>>>(src_idx, dst_idx, E);
    cudaEventRecord(s_join, s_side);

    // ---- main stream: GEMM chain (independent of CSR) ----
    gemm_pre_rb_kernel<<<pre_blocks, 256>>>(x, W_pre, b_pre, n);
    gemm_layer_rb_kernel<<<layer_blocks, 256>>>(Wl[0], n);

    // ---- join: gathers need both chains ----
    cudaStreamWaitEvent(0, s_join, 0);

    gather_kernel<false><<<gather_blocks, 256>>>(Bl[0], nullptr, n);
    // layer 2
    gemm_layer_rb_kernel<<<layer_blocks, 256>>>(Wl[1], n);
    gather_kernel<false><<<gather_blocks, 256>>>(Bl[1], nullptr, n);
    // layer 3 (+ L2 normalize)
    gemm_layer_rb_kernel<<<layer_blocks, 256>>>(Wl[2], n);
    gather_kernel<true><<<gather_blocks, 256>>>(Bl[2], out, n);
}